// round 12
// baseline (speedup 1.0000x reference)
#include <cuda_runtime.h>
#include <cuda_bf16.h>
#include <cstdint>
#include <math.h>

#define BSZ 4
#define TLEN 2048
#define CDIM 1024
#define BT (BSZ*TLEN)            // 8192
#define TOT ((long long)BT*CDIM)
#define N2 (CDIM*CDIM)

typedef __nv_bfloat16 bf16;

// ---------------- scratch (device globals; no cudaMalloc allowed) ----------
__device__ float g_q0[BT*CDIM];
__device__ float g_q1[BT*CDIM];
__device__ float g_vc[BT*CDIM];
__device__ float g_v [BT*CDIM];
__device__ float g_X0[N2];
__device__ float g_X1[N2];
__device__ float g_Am[N2];
__device__ float g_iw[CDIM];
__device__ bf16 g_ga_hi[BT*CDIM], g_ga_lo[BT*CDIM];     // x / (q*v) splits
__device__ bf16 g_qh[BT*CDIM],   g_ql[BT*CDIM];         // cur splits for scan
__device__ bf16 g_gb_hi[N2], g_gb_lo[N2];               // W_v / W_proj splits
__device__ bf16 g_gc_hi[N2], g_gc_lo[N2];               // W_up splits
__device__ bf16 g_xh[2][N2], g_xl[2][N2];               // X splits (ping-pong)
__device__ bf16 g_xth[2][N2], g_xtl[2][N2];             // X^T splits (ping-pong)
__device__ bf16 g_ah[N2], g_al[N2];                     // A = X^T X splits
__device__ bf16 g_sh[N2], g_sl[N2];                     // S splits

// ---------------- PTX helpers ----------------------------------------------
__device__ __forceinline__ uint32_t smem_u32(const void* p) {
    uint32_t a;
    asm("{ .reg .u64 t; cvta.to.shared.u64 t, %1; cvt.u32.u64 %0, t; }" : "=r"(a) : "l"(p));
    return a;
}
__device__ __forceinline__ void cp16(uint32_t dst, const void* src) {
    asm volatile("cp.async.cg.shared.global [%0], [%1], 16;" :: "r"(dst), "l"(src));
}
__device__ __forceinline__ void ldsm4(uint32_t a, uint32_t* r) {
    asm volatile("ldmatrix.sync.aligned.m8n8.x4.shared.b16 {%0,%1,%2,%3}, [%4];"
                 : "=r"(r[0]), "=r"(r[1]), "=r"(r[2]), "=r"(r[3]) : "r"(a));
}
__device__ __forceinline__ void mma16816(float* c, const uint32_t* a, const uint32_t* b) {
    asm volatile("mma.sync.aligned.m16n8k16.row.col.f32.bf16.bf16.f32 "
        "{%0,%1,%2,%3}, {%4,%5,%6,%7}, {%8,%9}, {%0,%1,%2,%3};"
        : "+f"(c[0]), "+f"(c[1]), "+f"(c[2]), "+f"(c[3])
        : "r"(a[0]), "r"(a[1]), "r"(a[2]), "r"(a[3]), "r"(b[0]), "r"(b[1]));
}
__device__ __forceinline__ uint32_t pk(float a, float b) {
    __nv_bfloat162 t(__float2bfloat16(a), __float2bfloat16(b));
    return *(uint32_t*)&t;
}

// ---------------- HMMA bf16-split GEMM --------------------------------------
// C[M,N] = alpha * (A @ B^T) + beta * Cin. A: MxK row-major, B: NxK row-major,
// K = 1024. A = Ahi+Alo, B = Bhi+Blo (3-product fp32 emulation).
// Warp grid WGM x WGN, warp tile 32x32, BK=32, 3-stage cp.async, single sync.
// big: 4x2 warps -> CTA 128x64, 256 thr, 92KB, 2 CTAs/SM (R7-proven)
// NS : 2x2 warps -> CTA  64x64, 128 thr, 61KB, 3 CTAs/SM (full-wave grid 256)
template<int WGM, int WGN, int OCC>
struct GP {
    static constexpr int BM      = 32*WGM;
    static constexpr int BN      = 32*WGN;
    static constexpr int THREADS = 32*WGM*WGN;
    static constexpr int RS      = 80;                 // smem row stride bytes
    static constexpr int TILE_A  = BM*RS;
    static constexpr int TILE_B  = BN*RS;
    static constexpr int STG     = 2*TILE_A + 2*TILE_B;
    static constexpr int SMEM    = 3*STG;
    static constexpr int LITERS  = (2*BM + 2*BN)*4/THREADS;
    static constexpr int NKT     = CDIM/32;
};

template<int WGM, int WGN, int OCC>
__device__ __forceinline__ void load_stage(uint32_t stg,
    const bf16* __restrict__ Ahi, const bf16* __restrict__ Alo,
    const bf16* __restrict__ Bhi, const bf16* __restrict__ Blo,
    int m0, int n0, int k0, int tid)
{
    using P = GP<WGM, WGN, OCC>;
    #pragma unroll
    for (int t = 0; t < P::LITERS; t++) {
        int i = tid + t*P::THREADS;
        int r_all = i >> 2;
        int c = (i & 3) << 3;
        uint32_t dst; const bf16* src;
        if (r_all < P::BM) {
            dst = stg + r_all*P::RS + c*2;
            src = Ahi + (long long)(m0+r_all)*CDIM + k0 + c;
        } else if (r_all < 2*P::BM) {
            int r = r_all - P::BM;
            dst = stg + P::TILE_A + r*P::RS + c*2;
            src = Alo + (long long)(m0+r)*CDIM + k0 + c;
        } else if (r_all < 2*P::BM + P::BN) {
            int r = r_all - 2*P::BM;
            dst = stg + 2*P::TILE_A + r*P::RS + c*2;
            src = Bhi + (long long)(n0+r)*CDIM + k0 + c;
        } else {
            int r = r_all - 2*P::BM - P::BN;
            dst = stg + 2*P::TILE_A + P::TILE_B + r*P::RS + c*2;
            src = Blo + (long long)(n0+r)*CDIM + k0 + c;
        }
        cp16(dst, src);
    }
}

template<int WGM, int WGN, int OCC>
__global__ void __launch_bounds__(32*WGM*WGN, OCC) mma_gemm(
    const bf16* __restrict__ Ahi, const bf16* __restrict__ Alo,
    const bf16* __restrict__ Bhi, const bf16* __restrict__ Blo,
    float* __restrict__ Cout, const float* __restrict__ Cin,
    bf16* __restrict__ Chi, bf16* __restrict__ Clo,
    bf16* __restrict__ CThi, bf16* __restrict__ CTlo,
    int M, int N, float alpha, float beta)
{
    using P = GP<WGM, WGN, OCC>;
    extern __shared__ char smem[];
    const uint32_t sb = smem_u32(smem);
    const int tid = threadIdx.x, wid = tid >> 5, lane = tid & 31;
    const int m0 = blockIdx.y * P::BM, n0 = blockIdx.x * P::BN;
    const int warp_m = wid % WGM;
    const int warp_n = wid / WGM;

    float acc[2][4][4];
    #pragma unroll
    for (int a = 0; a < 2; a++)
        #pragma unroll
        for (int b = 0; b < 4; b++)
            #pragma unroll
            for (int c = 0; c < 4; c++) acc[a][b][c] = 0.0f;

    const uint32_t a_base = (warp_m*32 + (lane & 15))*P::RS + ((lane >> 4) << 4);
    const uint32_t b_base = (warp_n*32 + (lane & 7) + ((lane >> 4) << 3))*P::RS
                          + (((lane >> 3) & 1) << 4);

    load_stage<WGM,WGN,OCC>(sb, Ahi, Alo, Bhi, Blo, m0, n0, 0, tid);
    asm volatile("cp.async.commit_group;" ::: "memory");
    load_stage<WGM,WGN,OCC>(sb + P::STG, Ahi, Alo, Bhi, Blo, m0, n0, 32, tid);
    asm volatile("cp.async.commit_group;" ::: "memory");

    for (int kt = 0; kt < P::NKT; kt++) {
        if (kt < P::NKT-1) asm volatile("cp.async.wait_group 1;" ::: "memory");
        else               asm volatile("cp.async.wait_group 0;" ::: "memory");
        __syncthreads();   // stage kt ready; all warps done reading stage (kt+2)%3
        if (kt + 2 < P::NKT) {
            load_stage<WGM,WGN,OCC>(sb + ((kt+2)%3)*P::STG, Ahi, Alo, Bhi, Blo,
                                    m0, n0, (kt+2)*32, tid);
            asm volatile("cp.async.commit_group;" ::: "memory");
        }

        const uint32_t stg = sb + (kt%3)*P::STG;
        #pragma unroll
        for (int kc = 0; kc < 2; kc++) {
            uint32_t ah[2][4], al[2][4], bh[2][4], bl[2][4];
            const uint32_t ao = stg + a_base + kc*32;
            ldsm4(ao,                          ah[0]);
            ldsm4(ao + 16*P::RS,               ah[1]);
            ldsm4(ao + P::TILE_A,              al[0]);
            ldsm4(ao + P::TILE_A + 16*P::RS,   al[1]);
            const uint32_t bo = stg + 2*P::TILE_A + b_base + kc*32;
            ldsm4(bo,                          bh[0]);
            ldsm4(bo + 16*P::RS,               bh[1]);
            ldsm4(bo + P::TILE_B,              bl[0]);
            ldsm4(bo + P::TILE_B + 16*P::RS,   bl[1]);
            #pragma unroll
            for (int mt = 0; mt < 2; mt++)
                #pragma unroll
                for (int nt = 0; nt < 4; nt++) {
                    const int n2 = nt >> 1, hf = (nt & 1) << 1;
                    mma16816(acc[mt][nt], ah[mt], &bh[n2][hf]);
                    mma16816(acc[mt][nt], ah[mt], &bl[n2][hf]);
                    mma16816(acc[mt][nt], al[mt], &bh[n2][hf]);
                }
        }
    }
    __syncthreads();   // compute done; smem free for epilogue staging

    // ---- epilogue ----
    constexpr int STRD = P::BN + 5;
    float* st = (float*)smem;
    const bool doCT = (CThi != nullptr);
    const int qr = lane >> 2, qc = (lane & 3) << 1;

    #pragma unroll
    for (int mt = 0; mt < 2; mt++) {
        #pragma unroll
        for (int nt = 0; nt < 4; nt++) {
            const int lr = warp_m*32 + mt*16 + qr;
            const int lc = warp_n*32 + nt*8 + qc;
            const int row = m0 + lr, col = n0 + lc;
            float* c = acc[mt][nt];
            const long long i0 = (long long)row*N + col;
            const long long i1 = (long long)(row+8)*N + col;
            float v0 = alpha*c[0], v1 = alpha*c[1], v2 = alpha*c[2], v3 = alpha*c[3];
            if (Cin) {
                float2 c0 = *(const float2*)(Cin + i0);
                float2 c1 = *(const float2*)(Cin + i1);
                v0 += beta*c0.x; v1 += beta*c0.y; v2 += beta*c1.x; v3 += beta*c1.y;
            }
            if (Cout) {
                *(float2*)(Cout + i0) = make_float2(v0, v1);
                *(float2*)(Cout + i1) = make_float2(v2, v3);
            }
            if (Chi) {
                uint32_t h0 = pk(v0, v1), h1 = pk(v2, v3);
                *(uint32_t*)(Chi + i0) = h0;
                *(uint32_t*)(Chi + i1) = h1;
                __nv_bfloat162 hh0 = *(__nv_bfloat162*)&h0;
                __nv_bfloat162 hh1 = *(__nv_bfloat162*)&h1;
                *(uint32_t*)(Clo + i0) = pk(v0 - __bfloat162float(hh0.x),
                                            v1 - __bfloat162float(hh0.y));
                *(uint32_t*)(Clo + i1) = pk(v2 - __bfloat162float(hh1.x),
                                            v3 - __bfloat162float(hh1.y));
            }
            if (doCT) {
                st[lr*STRD + lc]       = v0;
                st[lr*STRD + lc+1]     = v1;
                st[(lr+8)*STRD + lc]   = v2;
                st[(lr+8)*STRD + lc+1] = v3;
            }
        }
    }
    if (doCT) {
        __syncthreads();
        // write transposed splits: CT[(n0+n)*M + m0+m] = tile[m][n]
        constexpr int MH = P::BM/2;
        for (int idx = tid; idx < P::BN*MH; idx += P::THREADS) {
            const int n = idx / MH;
            const int m = (idx % MH) << 1;
            float v0 = st[m*STRD + n];
            float v1 = st[(m+1)*STRD + n];
            uint32_t h = pk(v0, v1);
            const long long o = (long long)(n0+n)*M + (m0+m);
            *(uint32_t*)(CThi + o) = h;
            __nv_bfloat162 hh = *(__nv_bfloat162*)&h;
            *(uint32_t*)(CTlo + o) = pk(v0 - __bfloat162float(hh.x),
                                        v1 - __bfloat162float(hh.y));
        }
    }
}

using GPbig = GP<4,2,2>;   // 128x64, 256 thr, 92KB, 2 CTAs/SM
using GPns  = GP<2,2,3>;   // 64x64,  128 thr, 61KB, 3 CTAs/SM

// ---------------- elementwise kernels (vectorized x4) ------------------------
__global__ void convert_split4(const float* __restrict__ src,
                               bf16* __restrict__ hi, bf16* __restrict__ lo, long long n4) {
    long long i = (long long)blockIdx.x*blockDim.x + threadIdx.x;
    if (i >= n4) return;
    long long i4 = i*4;
    float4 x = *(const float4*)(src + i4);
    uint32_t h0 = pk(x.x, x.y), h1 = pk(x.z, x.w);
    *(uint2*)(hi + i4) = make_uint2(h0, h1);
    __nv_bfloat162 a = *(__nv_bfloat162*)&h0, b = *(__nv_bfloat162*)&h1;
    *(uint2*)(lo + i4) = make_uint2(
        pk(x.x - __bfloat162float(a.x), x.y - __bfloat162float(a.y)),
        pk(x.z - __bfloat162float(b.x), x.w - __bfloat162float(b.y)));
}
__global__ void init_X(const float* __restrict__ src, float scale, float* __restrict__ X,
                       bf16* __restrict__ xh, bf16* __restrict__ xl,
                       bf16* __restrict__ xth, bf16* __restrict__ xtl) {
    __shared__ float t[32][33];
    const int bx = blockIdx.x*32, by = blockIdx.y*32;
    const int tx = threadIdx.x, ty = threadIdx.y;  // 32x8
    #pragma unroll
    for (int j = 0; j < 32; j += 8) {
        long long o = (long long)(by+ty+j)*CDIM + bx + tx;
        float v = src[o]*scale;
        X[o] = v;
        bf16 h = __float2bfloat16(v);
        xh[o] = h; xl[o] = __float2bfloat16(v - __bfloat162float(h));
        t[ty+j][tx] = v;
    }
    __syncthreads();
    #pragma unroll
    for (int j = 0; j < 32; j += 8) {
        float v = t[tx][ty+j];
        bf16 h = __float2bfloat16(v);
        long long o = (long long)(bx+ty+j)*CDIM + by + tx;
        xth[o] = h; xtl[o] = __float2bfloat16(v - __bfloat162float(h));
    }
}
__global__ void mul_split4(const float* __restrict__ a, const float* __restrict__ b,
                           bf16* __restrict__ hi, bf16* __restrict__ lo) {
    long long i = (long long)blockIdx.x*blockDim.x + threadIdx.x;
    if (i >= TOT/4) return;
    long long i4 = i*4;
    float4 x = *(const float4*)(a + i4);
    float4 y = *(const float4*)(b + i4);
    float s0 = x.x*y.x, s1 = x.y*y.y, s2 = x.z*y.z, s3 = x.w*y.w;
    uint32_t h0 = pk(s0, s1), h1 = pk(s2, s3);
    *(uint2*)(hi + i4) = make_uint2(h0, h1);
    __nv_bfloat162 p = *(__nv_bfloat162*)&h0, q = *(__nv_bfloat162*)&h1;
    *(uint2*)(lo + i4) = make_uint2(
        pk(s0 - __bfloat162float(p.x), s1 - __bfloat162float(p.y)),
        pk(s2 - __bfloat162float(q.x), s3 - __bfloat162float(q.y)));
}
// iw[n] = sum_k ident[k] * W[k*CDIM + n]
__global__ void ident_w(const float* __restrict__ ident, const float* __restrict__ W,
                        float* __restrict__ iw) {
    int n = blockIdx.x*blockDim.x + threadIdx.x;
    float s = 0.f;
    #pragma unroll 4
    for (int k = 0; k < CDIM; k++) s += ident[k]*W[(long long)k*CDIM + n];
    iw[n] = s;
}

// ---------------- combine: tiny 4-lane SDPA + rmsnorm per token -------------
// vc[t] = P[t] + (tt>=d ? P[t-d] : iw), where P = cur @ W (linearity of the mix).
__global__ void combine_kernel(const float* __restrict__ cur, const float* __restrict__ P,
                               const float* __restrict__ ident, const float* __restrict__ iw,
                               float* __restrict__ nxt, bf16* __restrict__ nh,
                               bf16* __restrict__ nl, int d) {
    const int t = blockIdx.x, tt = t % TLEN, j = threadIdx.x;
    const bool in = (tt >= d);
    const float* left  = in ? (cur + (long long)(t-d)*CDIM) : ident;
    const float* Pd    = in ? (P   + (long long)(t-d)*CDIM) : iw;
    const float* right = cur + (long long)t*CDIM;
    const float* Pt    = P   + (long long)t*CDIM;
    float l[4], r[4], w[4];
    #pragma unroll
    for (int i = 0; i < 4; i++) {
        l[i] = left [i*256+j];
        r[i] = right[i*256+j];
        w[i] = Pt[i*256+j] + Pd[i*256+j];
    }
    __shared__ float red[16][8];
    __shared__ float scores[16];
    __shared__ float scale_s[4];
    const int lane = j & 31, warp = j >> 5;
    #pragma unroll
    for (int q = 0; q < 16; q++) {
        float v = l[q>>2]*r[q&3];
        #pragma unroll
        for (int o = 16; o > 0; o >>= 1) v += __shfl_down_sync(0xffffffffu, v, o);
        if (lane == 0) red[q][warp] = v;
    }
    __syncthreads();
    if (j < 16) {
        float s = 0.f;
        #pragma unroll
        for (int wq = 0; wq < 8; wq++) s += red[j][wq];
        scores[j] = s * 0.0625f;
    }
    __syncthreads();
    float att[4][4];
    #pragma unroll
    for (int a = 0; a < 4; a++) {
        float mx = scores[a*4];
        #pragma unroll
        for (int b = 1; b < 4; b++) mx = fmaxf(mx, scores[a*4+b]);
        float sm = 0.f;
        #pragma unroll
        for (int b = 0; b < 4; b++) { att[a][b] = expf(scores[a*4+b]-mx); sm += att[a][b]; }
        float inv = 1.0f/sm;
        #pragma unroll
        for (int b = 0; b < 4; b++) att[a][b] *= inv;
    }
    float z[4];
    #pragma unroll
    for (int a = 0; a < 4; a++)
        z[a] = att[a][0]*w[0] + att[a][1]*w[1] + att[a][2]*w[2] + att[a][3]*w[3];
    __syncthreads();
    #pragma unroll
    for (int a = 0; a < 4; a++) {
        float v = z[a]*z[a];
        #pragma unroll
        for (int o = 16; o > 0; o >>= 1) v += __shfl_down_sync(0xffffffffu, v, o);
        if (lane == 0) red[a][warp] = v;
    }
    __syncthreads();
    if (j < 4) {
        float s = 0.f;
        #pragma unroll
        for (int wq = 0; wq < 8; wq++) s += red[j][wq];
        scale_s[j] = rsqrtf(s*(1.0f/256.0f) + 1e-8f) / (float)(j+1);
    }
    __syncthreads();
    float* o = nxt + (long long)t*CDIM;
    #pragma unroll
    for (int a = 0; a < 4; a++) {
        const long long idx = (long long)t*CDIM + a*256 + j;
        float ov = l[a] + z[a]*scale_s[a];
        o[a*256+j] = ov;
        if (nh) {
            bf16 h = __float2bfloat16(ov);
            nh[idx] = h;
            nl[idx] = __float2bfloat16(ov - __bfloat162float(h));
        }
    }
}

// ---------------- host orchestration ----------------------------------------
static inline void gemmBig(cudaStream_t s,
                           const bf16* Ahi, const bf16* Alo,
                           const bf16* Bhi, const bf16* Blo,
                           float* Cout, const float* Cin,
                           bf16* Chi, bf16* Clo,
                           int M, int N, float alpha, float beta)
{
    dim3 grid(N/GPbig::BN, M/GPbig::BM);
    mma_gemm<4,2,2><<<grid, GPbig::THREADS, GPbig::SMEM, s>>>(
        Ahi, Alo, Bhi, Blo, Cout, Cin, Chi, Clo, nullptr, nullptr, M, N, alpha, beta);
}
static inline void gemmNS(cudaStream_t s,
                          const bf16* Ahi, const bf16* Alo,
                          const bf16* Bhi, const bf16* Blo,
                          float* Cout, const float* Cin,
                          bf16* Chi, bf16* Clo, bf16* CThi, bf16* CTlo,
                          float alpha, float beta)
{
    dim3 grid(CDIM/GPns::BN, CDIM/GPns::BM);
    mma_gemm<2,2,3><<<grid, GPns::THREADS, GPns::SMEM, s>>>(
        Ahi, Alo, Bhi, Blo, Cout, Cin, Chi, Clo, CThi, CTlo, CDIM, CDIM, alpha, beta);
}

extern "C" void kernel_launch(void* const* d_in, const int* in_sizes, int n_in,
                              void* d_out, int out_size)
{
    const float* x      = (const float*)d_in[0];
    const float* W_up   = (const float*)d_in[1];
    const float* W_v    = (const float*)d_in[2];
    const float* W_proj = (const float*)d_in[3];
    const float* ident  = (const float*)d_in[4];
    const float* W_raw  = (const float*)d_in[5];
    float* out = (float*)d_out;
    const long long half = (long long)out_size / 2;

    static bool inited = false;
    static cudaStream_t s2;
    static cudaEvent_t e_fork, e_join;
    if (!inited) {
        cudaFuncSetAttribute(mma_gemm<4,2,2>, cudaFuncAttributeMaxDynamicSharedMemorySize, GPbig::SMEM);
        cudaFuncSetAttribute(mma_gemm<2,2,3>, cudaFuncAttributeMaxDynamicSharedMemorySize, GPns::SMEM);
        cudaStreamCreateWithFlags(&s2, cudaStreamNonBlocking);
        cudaEventCreateWithFlags(&e_fork, cudaEventDisableTiming);
        cudaEventCreateWithFlags(&e_join, cudaEventDisableTiming);
        inited = true;
    }
    cudaStream_t s0 = 0;

    float *q0,*q1,*vc,*v,*X0,*X1,*Am,*iwp;
    bf16 *gah,*gal,*qh,*ql,*gbh,*gbl,*gch,*gcl,*ah,*al,*sh,*sl;
    bf16 *xh[2],*xl[2],*xth[2],*xtl[2];
    cudaGetSymbolAddress((void**)&q0, g_q0);
    cudaGetSymbolAddress((void**)&q1, g_q1);
    cudaGetSymbolAddress((void**)&vc, g_vc);
    cudaGetSymbolAddress((void**)&v , g_v );
    cudaGetSymbolAddress((void**)&X0, g_X0);
    cudaGetSymbolAddress((void**)&X1, g_X1);
    cudaGetSymbolAddress((void**)&Am, g_Am);
    cudaGetSymbolAddress((void**)&iwp, g_iw);
    cudaGetSymbolAddress((void**)&gah, g_ga_hi); cudaGetSymbolAddress((void**)&gal, g_ga_lo);
    cudaGetSymbolAddress((void**)&qh, g_qh);     cudaGetSymbolAddress((void**)&ql, g_ql);
    cudaGetSymbolAddress((void**)&gbh, g_gb_hi); cudaGetSymbolAddress((void**)&gbl, g_gb_lo);
    cudaGetSymbolAddress((void**)&gch, g_gc_hi); cudaGetSymbolAddress((void**)&gcl, g_gc_lo);
    cudaGetSymbolAddress((void**)&ah, g_ah); cudaGetSymbolAddress((void**)&al, g_al);
    cudaGetSymbolAddress((void**)&sh, g_sh); cudaGetSymbolAddress((void**)&sl, g_sl);
    { bf16* p; cudaGetSymbolAddress((void**)&p, g_xh);  xh[0]=p;  xh[1]=p+N2; }
    { bf16* p; cudaGetSymbolAddress((void**)&p, g_xl);  xl[0]=p;  xl[1]=p+N2; }
    { bf16* p; cudaGetSymbolAddress((void**)&p, g_xth); xth[0]=p; xth[1]=p+N2; }
    { bf16* p; cudaGetSymbolAddress((void**)&p, g_xtl); xtl[0]=p; xtl[1]=p+N2; }

    const int wb4 = (N2/4 + 255)/256;
    const int eb4 = (int)((TOT/4 + 255)/256);
    dim3 tgrid(32, 32), tblk(32, 8);

    // ================= FORK: input GEMMs (no W dependency) on s2 ============
    cudaEventRecord(e_fork, s0);
    cudaStreamWaitEvent(s2, e_fork, 0);

    convert_split4<<<eb4,256,0,s2>>>(x, gah, gal, TOT/4);
    convert_split4<<<wb4,256,0,s2>>>(W_v, gbh, gbl, N2/4);
    gemmBig(s2, gah, gal, gbh, gbl, v, nullptr, nullptr, nullptr, BT, CDIM, 1.0f, 0.0f);
    convert_split4<<<wb4,256,0,s2>>>(W_up, gch, gcl, N2/4);
    gemmBig(s2, gah, gal, gch, gcl, q0, nullptr, qh, ql, BT, CDIM, 1.0f, 0.0f);
    cudaEventRecord(e_join, s2);

    // ================= s0: polar factor via quintic (Muon) + cubic polish ====
    init_X<<<tgrid, tblk, 0, s0>>>(W_raw, 1.0f/1.35f, X0, xh[0], xl[0], xth[0], xtl[0]);
    float* Xc = X0; float* Xn = X1;
    int pp = 0;
    const float qa = 3.4445f, qb = -4.7750f, qc5 = 2.0315f;
    for (int it = 0; it < 8; it++) {
        gemmNS(s0, xth[pp], xtl[pp], xth[pp], xtl[pp], Am, nullptr,
               ah, al, nullptr, nullptr, 1.0f, 0.0f);                 // A = X^T X
        gemmNS(s0, ah, al, ah, al, nullptr, Am,
               sh, sl, nullptr, nullptr, qc5, qb);                    // S = c*A^2 + b*A
        gemmNS(s0, xh[pp], xl[pp], sh, sl, Xn, Xc,
               xh[pp^1], xl[pp^1], xth[pp^1], xtl[pp^1], 1.0f, qa);   // Xn = X S + a X
        float* tmp = Xc; Xc = Xn; Xn = tmp; pp ^= 1;
    }
    for (int it = 0; it < 4; it++) {
        gemmNS(s0, xth[pp], xtl[pp], xth[pp], xtl[pp], nullptr, nullptr,
               ah, al, nullptr, nullptr, 1.0f, 0.0f);                 // A = X^T X
        gemmNS(s0, xh[pp], xl[pp], ah, al, Xn, Xc,
               xh[pp^1], xl[pp^1], xth[pp^1], xtl[pp^1], -0.5f, 1.5f);// Xn = 1.5X - 0.5 X A
        float* tmp = Xc; Xc = Xn; Xn = tmp; pp ^= 1;
    }
    bf16* wth = xth[pp];   // W^T splits for scan (P = cur @ W, NT form)
    bf16* wtl = xtl[pp];

    // iw = ident @ W  (W = Xc fp32, row-major)
    ident_w<<<CDIM/256, 256, 0, s0>>>(ident, Xc, iwp);

    // ================= JOIN =================================================
    cudaStreamWaitEvent(s0, e_join, 0);

    // ---- parallel scan: 11 Hillis-Steele steps ----
    float* cur = q0; float* nxt = q1;
    for (int d = 1; d < TLEN; d <<= 1) {
        gemmBig(s0, qh, ql, wth, wtl, vc, nullptr, nullptr, nullptr, BT, CDIM, 1.0f, 0.0f);
        const bool last = (2*d >= TLEN);
        combine_kernel<<<BT,256,0,s0>>>(cur, vc, ident, iwp, nxt,
                                        last ? nullptr : qh, last ? nullptr : ql, d);
        float* tmp = cur; cur = nxt; nxt = tmp;
    }

    // ---- Y = (q*v) @ W_proj^T ; write (Y, q) ----
    mul_split4<<<eb4,256,0,s0>>>(cur, v, gah, gal);
    convert_split4<<<wb4,256,0,s0>>>(W_proj, gbh, gbl, N2/4);
    gemmBig(s0, gah, gal, gbh, gbl, out, nullptr, nullptr, nullptr, BT, CDIM, 1.0f, 0.0f);
    cudaMemcpyAsync(out + half, cur, half*sizeof(float), cudaMemcpyDeviceToDevice, s0);
}

// round 14
// speedup vs baseline: 1.0066x; 1.0066x over previous
#include <cuda_runtime.h>
#include <cuda_bf16.h>
#include <cstdint>
#include <math.h>

#define BSZ 4
#define TLEN 2048
#define CDIM 1024
#define BT (BSZ*TLEN)            // 8192
#define TOT ((long long)BT*CDIM)
#define N2 (CDIM*CDIM)

typedef __nv_bfloat16 bf16;

// ---------------- scratch (device globals; no cudaMalloc allowed) ----------
__device__ float g_q0[BT*CDIM];          // final scan result fp32
__device__ float g_vc[BT*CDIM];
__device__ float g_v [BT*CDIM];
__device__ float g_X0[N2];
__device__ float g_X1[N2];
__device__ float g_Am[N2];
__device__ float g_iw[CDIM];
__device__ bf16 g_ga_hi[BT*CDIM], g_ga_lo[BT*CDIM];     // x / (q*v) splits
__device__ bf16 g_qh[2][BT*CDIM], g_ql[2][BT*CDIM];     // cur splits (ping-pong)
__device__ bf16 g_gb_hi[N2], g_gb_lo[N2];               // W_v / W_proj splits
__device__ bf16 g_gc_hi[N2], g_gc_lo[N2];               // W_up splits
__device__ bf16 g_xh[2][N2], g_xl[2][N2];               // X splits (ping-pong)
__device__ bf16 g_xth[2][N2], g_xtl[2][N2];             // X^T splits (ping-pong)
__device__ bf16 g_ah[N2], g_al[N2];                     // A = X^T X splits
__device__ bf16 g_sh[N2], g_sl[N2];                     // S splits

// ---------------- PTX helpers ----------------------------------------------
__device__ __forceinline__ uint32_t smem_u32(const void* p) {
    uint32_t a;
    asm("{ .reg .u64 t; cvta.to.shared.u64 t, %1; cvt.u32.u64 %0, t; }" : "=r"(a) : "l"(p));
    return a;
}
__device__ __forceinline__ void cp16(uint32_t dst, const void* src) {
    asm volatile("cp.async.cg.shared.global [%0], [%1], 16;" :: "r"(dst), "l"(src));
}
__device__ __forceinline__ void ldsm4(uint32_t a, uint32_t* r) {
    asm volatile("ldmatrix.sync.aligned.m8n8.x4.shared.b16 {%0,%1,%2,%3}, [%4];"
                 : "=r"(r[0]), "=r"(r[1]), "=r"(r[2]), "=r"(r[3]) : "r"(a));
}
__device__ __forceinline__ void mma16816(float* c, const uint32_t* a, const uint32_t* b) {
    asm volatile("mma.sync.aligned.m16n8k16.row.col.f32.bf16.bf16.f32 "
        "{%0,%1,%2,%3}, {%4,%5,%6,%7}, {%8,%9}, {%0,%1,%2,%3};"
        : "+f"(c[0]), "+f"(c[1]), "+f"(c[2]), "+f"(c[3])
        : "r"(a[0]), "r"(a[1]), "r"(a[2]), "r"(a[3]), "r"(b[0]), "r"(b[1]));
}
__device__ __forceinline__ uint32_t pk(float a, float b) {
    __nv_bfloat162 t(__float2bfloat16(a), __float2bfloat16(b));
    return *(uint32_t*)&t;
}

// ---------------- HMMA bf16-split GEMM (R7-proven shape) ---------------------
// C[M,N] = alpha * (A @ B^T) + beta * Cin. A: MxK row-major, B: NxK row-major,
// K = 1024. A = Ahi+Alo, B = Bhi+Blo (3-product fp32 emulation).
// CTA 128x64, 4x2 warps (32x32 warp tile), BK=32, 3-stage cp.async,
// single __syncthreads per K-tile, 92KB smem, 2 CTAs/SM.
struct GP {
    static constexpr int BM      = 128;
    static constexpr int BN      = 64;
    static constexpr int THREADS = 256;
    static constexpr int RS      = 80;                 // smem row stride bytes
    static constexpr int TILE_A  = BM*RS;              // 10240
    static constexpr int TILE_B  = BN*RS;              // 5120
    static constexpr int STG     = 2*TILE_A + 2*TILE_B;// 30720
    static constexpr int SMEM    = 3*STG;              // 92160
    static constexpr int NKT     = CDIM/32;            // 32
};

__device__ __forceinline__ void load_stage(uint32_t stg,
    const bf16* __restrict__ Ahi, const bf16* __restrict__ Alo,
    const bf16* __restrict__ Bhi, const bf16* __restrict__ Blo,
    int m0, int n0, int k0, int tid)
{
    #pragma unroll
    for (int t = 0; t < 6; t++) {
        int i = tid + t*256;
        int r_all = i >> 2;
        int c = (i & 3) << 3;
        uint32_t dst; const bf16* src;
        if (r_all < 128) {
            dst = stg + r_all*GP::RS + c*2;
            src = Ahi + (long long)(m0+r_all)*CDIM + k0 + c;
        } else if (r_all < 256) {
            int r = r_all - 128;
            dst = stg + GP::TILE_A + r*GP::RS + c*2;
            src = Alo + (long long)(m0+r)*CDIM + k0 + c;
        } else if (r_all < 320) {
            int r = r_all - 256;
            dst = stg + 2*GP::TILE_A + r*GP::RS + c*2;
            src = Bhi + (long long)(n0+r)*CDIM + k0 + c;
        } else {
            int r = r_all - 320;
            dst = stg + 2*GP::TILE_A + GP::TILE_B + r*GP::RS + c*2;
            src = Blo + (long long)(n0+r)*CDIM + k0 + c;
        }
        cp16(dst, src);
    }
}

__global__ void __launch_bounds__(256, 2) mma_gemm(
    const bf16* __restrict__ Ahi, const bf16* __restrict__ Alo,
    const bf16* __restrict__ Bhi, const bf16* __restrict__ Blo,
    float* __restrict__ Cout, const float* __restrict__ Cin,
    bf16* __restrict__ Chi, bf16* __restrict__ Clo,
    bf16* __restrict__ CThi, bf16* __restrict__ CTlo,
    int M, int N, float alpha, float beta)
{
    extern __shared__ char smem[];
    const uint32_t sb = smem_u32(smem);
    const int tid = threadIdx.x, wid = tid >> 5, lane = tid & 31;
    const int m0 = blockIdx.y * 128, n0 = blockIdx.x * 64;
    const int warp_m = wid & 3;
    const int warp_n = wid >> 2;

    float acc[2][4][4];
    #pragma unroll
    for (int a = 0; a < 2; a++)
        #pragma unroll
        for (int b = 0; b < 4; b++)
            #pragma unroll
            for (int c = 0; c < 4; c++) acc[a][b][c] = 0.0f;

    const uint32_t a_base = (warp_m*32 + (lane & 15))*GP::RS + ((lane >> 4) << 4);
    const uint32_t b_base = (warp_n*32 + (lane & 7) + ((lane >> 4) << 3))*GP::RS
                          + (((lane >> 3) & 1) << 4);

    load_stage(sb, Ahi, Alo, Bhi, Blo, m0, n0, 0, tid);
    asm volatile("cp.async.commit_group;" ::: "memory");
    load_stage(sb + GP::STG, Ahi, Alo, Bhi, Blo, m0, n0, 32, tid);
    asm volatile("cp.async.commit_group;" ::: "memory");

    for (int kt = 0; kt < GP::NKT; kt++) {
        if (kt < GP::NKT-1) asm volatile("cp.async.wait_group 1;" ::: "memory");
        else                asm volatile("cp.async.wait_group 0;" ::: "memory");
        __syncthreads();   // stage kt ready; all warps done reading stage (kt+2)%3
        if (kt + 2 < GP::NKT) {
            load_stage(sb + ((kt+2)%3)*GP::STG, Ahi, Alo, Bhi, Blo, m0, n0, (kt+2)*32, tid);
            asm volatile("cp.async.commit_group;" ::: "memory");
        }

        const uint32_t stg = sb + (kt%3)*GP::STG;
        #pragma unroll
        for (int kc = 0; kc < 2; kc++) {
            uint32_t ah[2][4], al[2][4], bh[2][4], bl[2][4];
            const uint32_t ao = stg + a_base + kc*32;
            ldsm4(ao,                           ah[0]);
            ldsm4(ao + 16*GP::RS,               ah[1]);
            ldsm4(ao + GP::TILE_A,              al[0]);
            ldsm4(ao + GP::TILE_A + 16*GP::RS,  al[1]);
            const uint32_t bo = stg + 2*GP::TILE_A + b_base + kc*32;
            ldsm4(bo,                           bh[0]);
            ldsm4(bo + 16*GP::RS,               bh[1]);
            ldsm4(bo + GP::TILE_B,              bl[0]);
            ldsm4(bo + GP::TILE_B + 16*GP::RS,  bl[1]);
            #pragma unroll
            for (int mt = 0; mt < 2; mt++)
                #pragma unroll
                for (int nt = 0; nt < 4; nt++) {
                    const int n2 = nt >> 1, hf = (nt & 1) << 1;
                    mma16816(acc[mt][nt], ah[mt], &bh[n2][hf]);
                    mma16816(acc[mt][nt], ah[mt], &bl[n2][hf]);
                    mma16816(acc[mt][nt], al[mt], &bh[n2][hf]);
                }
        }
    }
    __syncthreads();   // compute done; smem free for epilogue staging

    // ---- epilogue ----
    constexpr int STRD = 64 + 5;
    float* st = (float*)smem;
    const bool doCT = (CThi != nullptr);
    const int qr = lane >> 2, qc = (lane & 3) << 1;

    #pragma unroll
    for (int mt = 0; mt < 2; mt++) {
        #pragma unroll
        for (int nt = 0; nt < 4; nt++) {
            const int lr = warp_m*32 + mt*16 + qr;
            const int lc = warp_n*32 + nt*8 + qc;
            const int row = m0 + lr, col = n0 + lc;
            float* c = acc[mt][nt];
            const long long i0 = (long long)row*N + col;
            const long long i1 = (long long)(row+8)*N + col;
            float v0 = alpha*c[0], v1 = alpha*c[1], v2 = alpha*c[2], v3 = alpha*c[3];
            if (Cin) {
                float2 c0 = *(const float2*)(Cin + i0);
                float2 c1 = *(const float2*)(Cin + i1);
                v0 += beta*c0.x; v1 += beta*c0.y; v2 += beta*c1.x; v3 += beta*c1.y;
            }
            if (Cout) {
                *(float2*)(Cout + i0) = make_float2(v0, v1);
                *(float2*)(Cout + i1) = make_float2(v2, v3);
            }
            if (Chi) {
                uint32_t h0 = pk(v0, v1), h1 = pk(v2, v3);
                *(uint32_t*)(Chi + i0) = h0;
                *(uint32_t*)(Chi + i1) = h1;
                __nv_bfloat162 hh0 = *(__nv_bfloat162*)&h0;
                __nv_bfloat162 hh1 = *(__nv_bfloat162*)&h1;
                *(uint32_t*)(Clo + i0) = pk(v0 - __bfloat162float(hh0.x),
                                            v1 - __bfloat162float(hh0.y));
                *(uint32_t*)(Clo + i1) = pk(v2 - __bfloat162float(hh1.x),
                                            v3 - __bfloat162float(hh1.y));
            }
            if (doCT) {
                st[lr*STRD + lc]       = v0;
                st[lr*STRD + lc+1]     = v1;
                st[(lr+8)*STRD + lc]   = v2;
                st[(lr+8)*STRD + lc+1] = v3;
            }
        }
    }
    if (doCT) {
        __syncthreads();
        // write transposed splits: CT[(n0+n)*M + m0+m] = tile[m][n]
        for (int idx = tid; idx < 64*64; idx += 256) {
            const int n = idx >> 6;
            const int m = (idx & 63) << 1;
            float v0 = st[m*STRD + n];
            float v1 = st[(m+1)*STRD + n];
            uint32_t h = pk(v0, v1);
            const long long o = (long long)(n0+n)*M + (m0+m);
            *(uint32_t*)(CThi + o) = h;
            __nv_bfloat162 hh = *(__nv_bfloat162*)&h;
            *(uint32_t*)(CTlo + o) = pk(v0 - __bfloat162float(hh.x),
                                        v1 - __bfloat162float(hh.y));
        }
    }
}

// ---------------- elementwise kernels (vectorized x4) ------------------------
__global__ void convert_split4(const float* __restrict__ src,
                               bf16* __restrict__ hi, bf16* __restrict__ lo, long long n4) {
    long long i = (long long)blockIdx.x*blockDim.x + threadIdx.x;
    if (i >= n4) return;
    long long i4 = i*4;
    float4 x = *(const float4*)(src + i4);
    uint32_t h0 = pk(x.x, x.y), h1 = pk(x.z, x.w);
    *(uint2*)(hi + i4) = make_uint2(h0, h1);
    __nv_bfloat162 a = *(__nv_bfloat162*)&h0, b = *(__nv_bfloat162*)&h1;
    *(uint2*)(lo + i4) = make_uint2(
        pk(x.x - __bfloat162float(a.x), x.y - __bfloat162float(a.y)),
        pk(x.z - __bfloat162float(b.x), x.w - __bfloat162float(b.y)));
}
__global__ void init_X(const float* __restrict__ src, float scale, float* __restrict__ X,
                       bf16* __restrict__ xh, bf16* __restrict__ xl,
                       bf16* __restrict__ xth, bf16* __restrict__ xtl) {
    __shared__ float t[32][33];
    const int bx = blockIdx.x*32, by = blockIdx.y*32;
    const int tx = threadIdx.x, ty = threadIdx.y;  // 32x8
    #pragma unroll
    for (int j = 0; j < 32; j += 8) {
        long long o = (long long)(by+ty+j)*CDIM + bx + tx;
        float v = src[o]*scale;
        X[o] = v;
        bf16 h = __float2bfloat16(v);
        xh[o] = h; xl[o] = __float2bfloat16(v - __bfloat162float(h));
        t[ty+j][tx] = v;
    }
    __syncthreads();
    #pragma unroll
    for (int j = 0; j < 32; j += 8) {
        float v = t[tx][ty+j];
        bf16 h = __float2bfloat16(v);
        long long o = (long long)(bx+ty+j)*CDIM + by + tx;
        xth[o] = h; xtl[o] = __float2bfloat16(v - __bfloat162float(h));
    }
}
__global__ void mul_split4(const float* __restrict__ a, const float* __restrict__ b,
                           bf16* __restrict__ hi, bf16* __restrict__ lo) {
    long long i = (long long)blockIdx.x*blockDim.x + threadIdx.x;
    if (i >= TOT/4) return;
    long long i4 = i*4;
    float4 x = *(const float4*)(a + i4);
    float4 y = *(const float4*)(b + i4);
    float s0 = x.x*y.x, s1 = x.y*y.y, s2 = x.z*y.z, s3 = x.w*y.w;
    uint32_t h0 = pk(s0, s1), h1 = pk(s2, s3);
    *(uint2*)(hi + i4) = make_uint2(h0, h1);
    __nv_bfloat162 p = *(__nv_bfloat162*)&h0, q = *(__nv_bfloat162*)&h1;
    *(uint2*)(lo + i4) = make_uint2(
        pk(s0 - __bfloat162float(p.x), s1 - __bfloat162float(p.y)),
        pk(s2 - __bfloat162float(q.x), s3 - __bfloat162float(q.y)));
}
// iw[n] = sum_k ident[k] * W[k*CDIM + n]
__global__ void ident_w(const float* __restrict__ ident, const float* __restrict__ W,
                        float* __restrict__ iw) {
    int n = blockIdx.x*blockDim.x + threadIdx.x;
    float s = 0.f;
    #pragma unroll 4
    for (int k = 0; k < CDIM; k++) s += ident[k]*W[(long long)k*CDIM + n];
    iw[n] = s;
}

// ---------------- combine: tiny 4-lane SDPA + rmsnorm per token -------------
// cur is represented as hi+lo bf16 splits. vc[t] = P[t] + (tt>=d ? P[t-d] : iw).
// Emits next cur splits (nh/nl) and optionally fp32 (nxt, last step only).
__global__ void combine_kernel(const bf16* __restrict__ curh, const bf16* __restrict__ curl,
                               const float* __restrict__ P,
                               const float* __restrict__ ident, const float* __restrict__ iw,
                               float* __restrict__ nxt, bf16* __restrict__ nh,
                               bf16* __restrict__ nl, int d) {
    const int t = blockIdx.x, tt = t % TLEN, j = threadIdx.x;
    const bool in = (tt >= d);
    const long long base = (long long)t*CDIM;
    const long long sh = (long long)d*CDIM;
    float l[4], r[4], w[4];
    #pragma unroll
    for (int i = 0; i < 4; i++) {
        const long long it = base + i*256 + j;
        r[i] = __bfloat162float(curh[it]) + __bfloat162float(curl[it]);
        if (in) {
            l[i] = __bfloat162float(curh[it - sh]) + __bfloat162float(curl[it - sh]);
            w[i] = P[it] + P[it - sh];
        } else {
            l[i] = ident[i*256 + j];
            w[i] = P[it] + iw[i*256 + j];
        }
    }
    __shared__ float red[16][8];
    __shared__ float scores[16];
    __shared__ float scale_s[4];
    const int lane = j & 31, warp = j >> 5;
    #pragma unroll
    for (int q = 0; q < 16; q++) {
        float v = l[q>>2]*r[q&3];
        #pragma unroll
        for (int o = 16; o > 0; o >>= 1) v += __shfl_down_sync(0xffffffffu, v, o);
        if (lane == 0) red[q][warp] = v;
    }
    __syncthreads();
    if (j < 16) {
        float s = 0.f;
        #pragma unroll
        for (int wq = 0; wq < 8; wq++) s += red[j][wq];
        scores[j] = s * 0.0625f;
    }
    __syncthreads();
    float att[4][4];
    #pragma unroll
    for (int a = 0; a < 4; a++) {
        float mx = scores[a*4];
        #pragma unroll
        for (int b = 1; b < 4; b++) mx = fmaxf(mx, scores[a*4+b]);
        float sm = 0.f;
        #pragma unroll
        for (int b = 0; b < 4; b++) { att[a][b] = expf(scores[a*4+b]-mx); sm += att[a][b]; }
        float inv = 1.0f/sm;
        #pragma unroll
        for (int b = 0; b < 4; b++) att[a][b] *= inv;
    }
    float z[4];
    #pragma unroll
    for (int a = 0; a < 4; a++)
        z[a] = att[a][0]*w[0] + att[a][1]*w[1] + att[a][2]*w[2] + att[a][3]*w[3];
    __syncthreads();
    #pragma unroll
    for (int a = 0; a < 4; a++) {
        float v = z[a]*z[a];
        #pragma unroll
        for (int o = 16; o > 0; o >>= 1) v += __shfl_down_sync(0xffffffffu, v, o);
        if (lane == 0) red[a][warp] = v;
    }
    __syncthreads();
    if (j < 4) {
        float s = 0.f;
        #pragma unroll
        for (int wq = 0; wq < 8; wq++) s += red[j][wq];
        scale_s[j] = rsqrtf(s*(1.0f/256.0f) + 1e-8f) / (float)(j+1);
    }
    __syncthreads();
    #pragma unroll
    for (int a = 0; a < 4; a++) {
        const long long idx = base + a*256 + j;
        float ov = l[a] + z[a]*scale_s[a];
        if (nxt) nxt[idx] = ov;
        if (nh) {
            bf16 h = __float2bfloat16(ov);
            nh[idx] = h;
            nl[idx] = __float2bfloat16(ov - __bfloat162float(h));
        }
    }
}

// ---------------- host orchestration ----------------------------------------
static inline void gemm3(cudaStream_t s,
                         const bf16* Ahi, const bf16* Alo,
                         const bf16* Bhi, const bf16* Blo,
                         float* Cout, const float* Cin,
                         bf16* Chi, bf16* Clo, bf16* CThi, bf16* CTlo,
                         int M, int N, float alpha, float beta)
{
    dim3 grid(N/64, M/128);
    mma_gemm<<<grid, 256, GP::SMEM, s>>>(
        Ahi, Alo, Bhi, Blo, Cout, Cin, Chi, Clo, CThi, CTlo, M, N, alpha, beta);
}

extern "C" void kernel_launch(void* const* d_in, const int* in_sizes, int n_in,
                              void* d_out, int out_size)
{
    const float* x      = (const float*)d_in[0];
    const float* W_up   = (const float*)d_in[1];
    const float* W_v    = (const float*)d_in[2];
    const float* W_proj = (const float*)d_in[3];
    const float* ident  = (const float*)d_in[4];
    const float* W_raw  = (const float*)d_in[5];
    float* out = (float*)d_out;
    const long long half = (long long)out_size / 2;

    static bool inited = false;
    static cudaStream_t s2;
    static cudaEvent_t e_fork, e_join;
    if (!inited) {
        cudaFuncSetAttribute(mma_gemm, cudaFuncAttributeMaxDynamicSharedMemorySize, GP::SMEM);
        cudaStreamCreateWithFlags(&s2, cudaStreamNonBlocking);
        cudaEventCreateWithFlags(&e_fork, cudaEventDisableTiming);
        cudaEventCreateWithFlags(&e_join, cudaEventDisableTiming);
        inited = true;
    }
    cudaStream_t s0 = 0;

    float *q0,*vc,*v,*X0,*X1,*Am,*iwp;
    bf16 *gah,*gal,*gbh,*gbl,*gch,*gcl,*ah,*al,*sh,*sl;
    bf16 *qh[2],*ql[2],*xh[2],*xl[2],*xth[2],*xtl[2];
    cudaGetSymbolAddress((void**)&q0, g_q0);
    cudaGetSymbolAddress((void**)&vc, g_vc);
    cudaGetSymbolAddress((void**)&v , g_v );
    cudaGetSymbolAddress((void**)&X0, g_X0);
    cudaGetSymbolAddress((void**)&X1, g_X1);
    cudaGetSymbolAddress((void**)&Am, g_Am);
    cudaGetSymbolAddress((void**)&iwp, g_iw);
    cudaGetSymbolAddress((void**)&gah, g_ga_hi); cudaGetSymbolAddress((void**)&gal, g_ga_lo);
    cudaGetSymbolAddress((void**)&gbh, g_gb_hi); cudaGetSymbolAddress((void**)&gbl, g_gb_lo);
    cudaGetSymbolAddress((void**)&gch, g_gc_hi); cudaGetSymbolAddress((void**)&gcl, g_gc_lo);
    cudaGetSymbolAddress((void**)&ah, g_ah); cudaGetSymbolAddress((void**)&al, g_al);
    cudaGetSymbolAddress((void**)&sh, g_sh); cudaGetSymbolAddress((void**)&sl, g_sl);
    { bf16* p; cudaGetSymbolAddress((void**)&p, g_qh);  qh[0]=p;  qh[1]=p+BT*CDIM; }
    { bf16* p; cudaGetSymbolAddress((void**)&p, g_ql);  ql[0]=p;  ql[1]=p+BT*CDIM; }
    { bf16* p; cudaGetSymbolAddress((void**)&p, g_xh);  xh[0]=p;  xh[1]=p+N2; }
    { bf16* p; cudaGetSymbolAddress((void**)&p, g_xl);  xl[0]=p;  xl[1]=p+N2; }
    { bf16* p; cudaGetSymbolAddress((void**)&p, g_xth); xth[0]=p; xth[1]=p+N2; }
    { bf16* p; cudaGetSymbolAddress((void**)&p, g_xtl); xtl[0]=p; xtl[1]=p+N2; }

    const int wb4 = (N2/4 + 255)/256;
    const int eb4 = (int)((TOT/4 + 255)/256);
    dim3 tgrid(32, 32), tblk(32, 8);

    // ================= FORK: input GEMMs (no W dependency) on s2 ============
    cudaEventRecord(e_fork, s0);
    cudaStreamWaitEvent(s2, e_fork, 0);

    convert_split4<<<eb4,256,0,s2>>>(x, gah, gal, TOT/4);
    convert_split4<<<wb4,256,0,s2>>>(W_v, gbh, gbl, N2/4);
    gemm3(s2, gah, gal, gbh, gbl, v, nullptr, nullptr, nullptr, nullptr, nullptr,
          BT, CDIM, 1.0f, 0.0f);
    convert_split4<<<wb4,256,0,s2>>>(W_up, gch, gcl, N2/4);
    gemm3(s2, gah, gal, gch, gcl, nullptr, nullptr, qh[0], ql[0], nullptr, nullptr,
          BT, CDIM, 1.0f, 0.0f);
    cudaEventRecord(e_join, s2);

    // ================= s0: polar factor (8 quintic + 4 cubic, all 3-product) ==
    init_X<<<tgrid, tblk, 0, s0>>>(W_raw, 1.0f/1.35f, X0, xh[0], xl[0], xth[0], xtl[0]);
    float* Xc = X0; float* Xn = X1;
    int pp = 0;
    const float qa = 3.4445f, qb = -4.7750f, qc5 = 2.0315f;
    for (int it = 0; it < 8; it++) {
        gemm3(s0, xth[pp], xtl[pp], xth[pp], xtl[pp], Am, nullptr,
              ah, al, nullptr, nullptr, CDIM, CDIM, 1.0f, 0.0f);          // A = X^T X
        gemm3(s0, ah, al, ah, al, nullptr, Am,
              sh, sl, nullptr, nullptr, CDIM, CDIM, qc5, qb);             // S = c*A^2 + b*A
        gemm3(s0, xh[pp], xl[pp], sh, sl, Xn, Xc,
              xh[pp^1], xl[pp^1], xth[pp^1], xtl[pp^1], CDIM, CDIM, 1.0f, qa); // Xn = X S + a X
        float* tmp = Xc; Xc = Xn; Xn = tmp; pp ^= 1;
    }
    for (int it = 0; it < 4; it++) {
        gemm3(s0, xth[pp], xtl[pp], xth[pp], xtl[pp], nullptr, nullptr,
              ah, al, nullptr, nullptr, CDIM, CDIM, 1.0f, 0.0f);          // A = X^T X
        gemm3(s0, xh[pp], xl[pp], ah, al, Xn, Xc,
              xh[pp^1], xl[pp^1], xth[pp^1], xtl[pp^1], CDIM, CDIM, -0.5f, 1.5f);
        float* tmp = Xc; Xc = Xn; Xn = tmp; pp ^= 1;
    }
    bf16* wth = xth[pp];   // W^T splits for scan (P = cur @ W, NT form)
    bf16* wtl = xtl[pp];

    // iw = ident @ W  (W = Xc fp32, row-major)
    ident_w<<<CDIM/256, 256, 0, s0>>>(ident, Xc, iwp);

    // ================= JOIN =================================================
    cudaStreamWaitEvent(s0, e_join, 0);

    // ---- parallel scan: 11 Hillis-Steele steps (cur kept as bf16 splits) ----
    int sp = 0;
    for (int d = 1; d < TLEN; d <<= 1) {
        gemm3(s0, qh[sp], ql[sp], wth, wtl, vc, nullptr, nullptr, nullptr, nullptr, nullptr,
              BT, CDIM, 1.0f, 0.0f);                                      // P = cur @ W
        const bool last = (2*d >= TLEN);
        combine_kernel<<<BT,256,0,s0>>>(qh[sp], ql[sp], vc, ident, iwp,
                                        last ? q0 : nullptr,
                                        last ? nullptr : qh[sp^1],
                                        last ? nullptr : ql[sp^1], d);
        sp ^= 1;
    }

    // ---- Y = (q*v) @ W_proj^T ; write (Y, q) ----
    mul_split4<<<eb4,256,0,s0>>>(q0, v, gah, gal);
    convert_split4<<<wb4,256,0,s0>>>(W_proj, gbh, gbl, N2/4);
    gemm3(s0, gah, gal, gbh, gbl, out, nullptr, nullptr, nullptr, nullptr, nullptr,
          BT, CDIM, 1.0f, 0.0f);
    cudaMemcpyAsync(out + half, q0, half*sizeof(float), cudaMemcpyDeviceToDevice, s0);
}